// round 13
// baseline (speedup 1.0000x reference)
#include <cuda_runtime.h>
#include <cuda_bf16.h>

#define KC 16
#define DD 16
#define NQUAD 136          // i<=j pairs
#define NFEAT 152          // 136 quad + 16 linear
#define NALL  (NFEAT + 1)  // + constants row

// Staging area written by the precompute kernel (single symbol -> single copy).
__device__ float g_all[NALL * KC];
// Constant-bank mirror: hot loop reads via uniform-path loads (LDCU).
__constant__ __align__(16) float c_all[NALL * KC];

// ---------------------------------------------------------------------------
// f32x2 packed helpers
// ---------------------------------------------------------------------------
__device__ __forceinline__ unsigned long long f2dup(float v) {
    unsigned long long r;
    asm("mov.b64 %0, {%1, %1};" : "=l"(r) : "f"(v));
    return r;
}
__device__ __forceinline__ unsigned long long f2fma(unsigned long long a, unsigned long long b,
                                                    unsigned long long c) {
    unsigned long long r;
    asm("fma.rn.f32x2 %0, %1, %2, %3;" : "=l"(r) : "l"(a), "l"(b), "l"(c));
    return r;
}
__device__ __forceinline__ void f2unpack(unsigned long long v, float& lo, float& hi) {
    asm("mov.b64 {%0, %1}, %2;" : "=f"(lo), "=f"(hi) : "l"(v));
}

// ---------------------------------------------------------------------------
// Precompute: one warp-block per cluster (16 blocks on 16 SMs concurrently).
// Gauss-Jordan inverse of Sigma, logdet from pivots, b = P*mu.
// ---------------------------------------------------------------------------
__global__ void gmm_precompute(const float* __restrict__ pi,
                               const float* __restrict__ mu,
                               const float* __restrict__ Sigma) {
    const int w    = blockIdx.x;
    const int lane = threadIdx.x & 31;
    const int j    = lane & 15;

    float a[16], inv[16];
#pragma unroll
    for (int i = 0; i < 16; ++i) {
        a[i]   = Sigma[w * 256 + i * 16 + j];
        inv[i] = (i == j) ? 1.0f : 0.0f;
    }

    float logdet = 0.0f;
#pragma unroll
    for (int k = 0; k < 16; ++k) {
        float piv = __shfl_sync(0xffffffffu, a[k], k);
        logdet += logf(piv);
        float ip = 1.0f / piv;
        a[k]   *= ip;
        inv[k] *= ip;
#pragma unroll
        for (int i = 0; i < 16; ++i) {
            if (i != k) {
                float m = __shfl_sync(0xffffffffu, a[i], k);
                a[i]   = fmaf(-m, a[k],   a[i]);
                inv[i] = fmaf(-m, inv[k], inv[i]);
            }
        }
    }

    const float mu_j = mu[w * 16 + j];
    float bv[16];
#pragma unroll
    for (int i = 0; i < 16; ++i) {
        float v = inv[i] * mu_j;
        v += __shfl_xor_sync(0xffffffffu, v, 8);
        v += __shfl_xor_sync(0xffffffffu, v, 4);
        v += __shfl_xor_sync(0xffffffffu, v, 2);
        v += __shfl_xor_sync(0xffffffffu, v, 1);
        bv[i] = v;
    }
    float muPmu = 0.0f;
#pragma unroll
    for (int i = 0; i < 16; ++i) muPmu += bv[i] * mu[w * 16 + i];

    if (lane < 16) {
#pragma unroll
        for (int i = 0; i < 16; ++i) {
            if (i <= j) {
                float c = (i == j ? -0.5f : -1.0f) * inv[i];
                g_all[(j * (j + 1) / 2 + i) * KC + w] = c;
            }
        }
    }
    if (lane == 0) {
#pragma unroll
        for (int i = 0; i < 16; ++i) g_all[(NQUAD + i) * KC + w] = bv[i];
        g_all[NFEAT * KC + w] =
            logf(pi[w]) - 0.5f * logdet - 8.0f * 1.8378770664093453f - 0.5f * muPmu;
    }
}

// ---------------------------------------------------------------------------
// softmax + float4 store for one point's 16 logits
// ---------------------------------------------------------------------------
__device__ __forceinline__ void softmax_store(const float* l, float* outp) {
    float mx = l[0];
#pragma unroll
    for (int k = 1; k < 16; ++k) mx = fmaxf(mx, l[k]);
    float e[16], s = 0.0f;
#pragma unroll
    for (int k = 0; k < 16; ++k) { e[k] = __expf(l[k] - mx); s += e[k]; }
    float r = __fdividef(1.0f, s);
    float4* o = reinterpret_cast<float4*>(outp);
    o[0] = make_float4(e[0] * r,  e[1] * r,  e[2] * r,  e[3] * r);
    o[1] = make_float4(e[4] * r,  e[5] * r,  e[6] * r,  e[7] * r);
    o[2] = make_float4(e[8] * r,  e[9] * r,  e[10] * r, e[11] * r);
    o[3] = make_float4(e[12] * r, e[13] * r, e[14] * r, e[15] * r);
}

// ---------------------------------------------------------------------------
// Per-feature body: scalar products for 2 points, ALU dup-movs, then 16 f2fma
// against ONE set of 4 LDCU.128 coefficient loads shared by both points.
// ---------------------------------------------------------------------------
__device__ __forceinline__ void accum_feature(float pA, float pB,
                                              const ulonglong2* cp,
                                              unsigned long long* accA,
                                              unsigned long long* accB) {
    unsigned long long fA = f2dup(pA);
    unsigned long long fB = f2dup(pB);
#pragma unroll
    for (int m = 0; m < 4; ++m) {
        ulonglong2 cc = cp[m];                 // clusters 4m..4m+3 (one LDCU.128)
        accA[2 * m]     = f2fma(cc.x, fA, accA[2 * m]);
        accA[2 * m + 1] = f2fma(cc.y, fA, accA[2 * m + 1]);
        accB[2 * m]     = f2fma(cc.x, fB, accB[2 * m]);
        accB[2 * m + 1] = f2fma(cc.y, fB, accB[2 * m + 1]);
    }
}

// ---------------------------------------------------------------------------
// Main kernel: 2 points/thread, scalar X (32 regs), cluster-packed acc
// (32 regs), constant-bank coefficients. Block=128 with 6 CTAs/SM: same
// 24 warps/SM as the 256x3 config, but half-size CTAs halve the wave-
// quantization tail (977 CTAs @6.6/SM -> 1954 @13.2/SM).
// ---------------------------------------------------------------------------
__global__ void __launch_bounds__(128, 6) gmm_main(const float* __restrict__ x,
                                                   float* __restrict__ out, int n) {
    long long t  = (long long)blockIdx.x * blockDim.x + threadIdx.x;
    long long n0 = 2 * t;
    if (n0 >= n) return;
    const bool hasB = (n0 + 1 < n);

    const float4* x4A = reinterpret_cast<const float4*>(x + n0 * DD);
    const float4* x4B = reinterpret_cast<const float4*>(x + (hasB ? (n0 + 1) : n0) * DD);

    float xA[16], xB[16];
#pragma unroll
    for (int q = 0; q < 4; ++q) {
        float4 va = x4A[q], vb = x4B[q];
        xA[4 * q + 0] = va.x; xA[4 * q + 1] = va.y; xA[4 * q + 2] = va.z; xA[4 * q + 3] = va.w;
        xB[4 * q + 0] = vb.x; xB[4 * q + 1] = vb.y; xB[4 * q + 2] = vb.z; xB[4 * q + 3] = vb.w;
    }

    const ulonglong2* cvec = reinterpret_cast<const ulonglong2*>(c_all);

    unsigned long long accA[8], accB[8];
#pragma unroll
    for (int m = 0; m < 4; ++m) {
        ulonglong2 c = cvec[NFEAT * 4 + m];   // constants row
        accA[2 * m]     = c.x; accB[2 * m]     = c.x;
        accA[2 * m + 1] = c.y; accB[2 * m + 1] = c.y;
    }

    // quadratic features (i<=j), feature p = j*(j+1)/2 + i
    int p = 0;
#pragma unroll
    for (int j = 0; j < 16; ++j) {
#pragma unroll
        for (int i = 0; i <= j; ++i) {
            accum_feature(xA[i] * xA[j], xB[i] * xB[j], cvec + p * 4, accA, accB);
            ++p;
        }
    }
    // linear features
#pragma unroll
    for (int i = 0; i < 16; ++i)
        accum_feature(xA[i], xB[i], cvec + (NQUAD + i) * 4, accA, accB);

    // unpack logits
    float la[16], lb[16];
#pragma unroll
    for (int m = 0; m < 8; ++m) {
        f2unpack(accA[m], la[2 * m], la[2 * m + 1]);
        f2unpack(accB[m], lb[2 * m], lb[2 * m + 1]);
    }

    softmax_store(la, out + n0 * KC);
    if (hasB) softmax_store(lb, out + (n0 + 1) * KC);
}

extern "C" void kernel_launch(void* const* d_in, const int* in_sizes, int n_in,
                              void* d_out, int out_size) {
    const float* x     = (const float*)d_in[0];
    const float* pi    = (const float*)d_in[1];
    const float* mu    = (const float*)d_in[2];
    const float* Sigma = (const float*)d_in[3];
    float* out = (float*)d_out;

    int n = in_sizes[0] / DD;

    // 16 blocks, one warp-block per cluster: runs on 16 SMs in parallel.
    gmm_precompute<<<KC, 32>>>(pi, mu, Sigma);

    void* gall_addr = nullptr;
    cudaGetSymbolAddress(&gall_addr, g_all);
    cudaMemcpyToSymbolAsync(c_all, gall_addr, sizeof(float) * NALL * KC, 0,
                            cudaMemcpyDeviceToDevice, 0);

    int nthreads = (n + 1) / 2;   // 2 points per thread
    int block = 128;
    int grid  = (nthreads + block - 1) / block;
    gmm_main<<<grid, block>>>(x, out, n);
}

// round 14
// speedup vs baseline: 1.1490x; 1.1490x over previous
#include <cuda_runtime.h>
#include <cuda_bf16.h>

#define KC 16
#define DD 16
#define NQUAD 136          // i<=j pairs
#define NFEAT 152          // 136 quad + 16 linear
#define NALL  (NFEAT + 1)  // + constants row

// Staging area written by the precompute kernel (single symbol -> single copy).
__device__ float g_all[NALL * KC];
// Constant-bank mirror: hot loop reads via uniform-path loads (LDCU).
__constant__ __align__(16) float c_all[NALL * KC];

// ---------------------------------------------------------------------------
// f32x2 packed helpers
// ---------------------------------------------------------------------------
__device__ __forceinline__ unsigned long long f2dup(float v) {
    unsigned long long r;
    asm("mov.b64 %0, {%1, %1};" : "=l"(r) : "f"(v));
    return r;
}
__device__ __forceinline__ unsigned long long f2fma(unsigned long long a, unsigned long long b,
                                                    unsigned long long c) {
    unsigned long long r;
    asm("fma.rn.f32x2 %0, %1, %2, %3;" : "=l"(r) : "l"(a), "l"(b), "l"(c));
    return r;
}
__device__ __forceinline__ void f2unpack(unsigned long long v, float& lo, float& hi) {
    asm("mov.b64 {%0, %1}, %2;" : "=f"(lo), "=f"(hi) : "l"(v));
}

// ---------------------------------------------------------------------------
// Precompute: one warp-block per cluster (16 blocks run on 16 SMs in
// parallel). Gauss-Jordan inverse of Sigma, logdet from pivots, b = P*mu.
// ---------------------------------------------------------------------------
__global__ void gmm_precompute(const float* __restrict__ pi,
                               const float* __restrict__ mu,
                               const float* __restrict__ Sigma) {
    const int w    = blockIdx.x;
    const int lane = threadIdx.x & 31;
    const int j    = lane & 15;

    float a[16], inv[16];
#pragma unroll
    for (int i = 0; i < 16; ++i) {
        a[i]   = Sigma[w * 256 + i * 16 + j];
        inv[i] = (i == j) ? 1.0f : 0.0f;
    }

    float logdet = 0.0f;
#pragma unroll
    for (int k = 0; k < 16; ++k) {
        float piv = __shfl_sync(0xffffffffu, a[k], k);
        logdet += logf(piv);
        float ip = 1.0f / piv;
        a[k]   *= ip;
        inv[k] *= ip;
#pragma unroll
        for (int i = 0; i < 16; ++i) {
            if (i != k) {
                float m = __shfl_sync(0xffffffffu, a[i], k);
                a[i]   = fmaf(-m, a[k],   a[i]);
                inv[i] = fmaf(-m, inv[k], inv[i]);
            }
        }
    }

    const float mu_j = mu[w * 16 + j];
    float bv[16];
#pragma unroll
    for (int i = 0; i < 16; ++i) {
        float v = inv[i] * mu_j;
        v += __shfl_xor_sync(0xffffffffu, v, 8);
        v += __shfl_xor_sync(0xffffffffu, v, 4);
        v += __shfl_xor_sync(0xffffffffu, v, 2);
        v += __shfl_xor_sync(0xffffffffu, v, 1);
        bv[i] = v;
    }
    float muPmu = 0.0f;
#pragma unroll
    for (int i = 0; i < 16; ++i) muPmu += bv[i] * mu[w * 16 + i];

    if (lane < 16) {
#pragma unroll
        for (int i = 0; i < 16; ++i) {
            if (i <= j) {
                float c = (i == j ? -0.5f : -1.0f) * inv[i];
                g_all[(j * (j + 1) / 2 + i) * KC + w] = c;
            }
        }
    }
    if (lane == 0) {
#pragma unroll
        for (int i = 0; i < 16; ++i) g_all[(NQUAD + i) * KC + w] = bv[i];
        g_all[NFEAT * KC + w] =
            logf(pi[w]) - 0.5f * logdet - 8.0f * 1.8378770664093453f - 0.5f * muPmu;
    }
}

// ---------------------------------------------------------------------------
// Main kernel (R9 best-total config, verbatim): ONE point per thread.
// X scalar (16 regs), acc packs 2 clusters per f32x2 (16 regs). Per feature:
// 1 FMUL + 1 ALU dup-mov + 4 LDCU.128 + 8 f2fma. 39 regs -> 5 CTAs/SM.
// ---------------------------------------------------------------------------
__global__ void __launch_bounds__(256, 5) gmm_main(const float* __restrict__ x,
                                                   float* __restrict__ out, int n) {
    long long t = (long long)blockIdx.x * blockDim.x + threadIdx.x;
    if (t >= n) return;

    const float4* x4 = reinterpret_cast<const float4*>(x + t * DD);
    float X[16];
#pragma unroll
    for (int q = 0; q < 4; ++q) {
        float4 v = x4[q];
        X[4 * q + 0] = v.x; X[4 * q + 1] = v.y; X[4 * q + 2] = v.z; X[4 * q + 3] = v.w;
    }

    const ulonglong2* cvec = reinterpret_cast<const ulonglong2*>(c_all);

    unsigned long long acc[8];
#pragma unroll
    for (int m = 0; m < 4; ++m) {
        ulonglong2 c = cvec[NFEAT * 4 + m];   // constants row
        acc[2 * m] = c.x; acc[2 * m + 1] = c.y;
    }

    // quadratic features (i<=j), feature p = j*(j+1)/2 + i
    int p = 0;
#pragma unroll
    for (int j = 0; j < 16; ++j) {
#pragma unroll
        for (int i = 0; i <= j; ++i) {
            unsigned long long f = f2dup(X[i] * X[j]);
#pragma unroll
            for (int m = 0; m < 4; ++m) {
                ulonglong2 cc = cvec[p * 4 + m];      // clusters 4m..4m+3
                acc[2 * m]     = f2fma(cc.x, f, acc[2 * m]);
                acc[2 * m + 1] = f2fma(cc.y, f, acc[2 * m + 1]);
            }
            ++p;
        }
    }
    // linear features
#pragma unroll
    for (int i = 0; i < 16; ++i) {
        unsigned long long f = f2dup(X[i]);
#pragma unroll
        for (int m = 0; m < 4; ++m) {
            ulonglong2 cc = cvec[(NQUAD + i) * 4 + m];
            acc[2 * m]     = f2fma(cc.x, f, acc[2 * m]);
            acc[2 * m + 1] = f2fma(cc.y, f, acc[2 * m + 1]);
        }
    }

    // unpack logits
    float l[16];
#pragma unroll
    for (int m = 0; m < 8; ++m) f2unpack(acc[m], l[2 * m], l[2 * m + 1]);

    // softmax + store
    float mx = l[0];
#pragma unroll
    for (int k = 1; k < 16; ++k) mx = fmaxf(mx, l[k]);
    float e[16], s = 0.0f;
#pragma unroll
    for (int k = 0; k < 16; ++k) { e[k] = __expf(l[k] - mx); s += e[k]; }
    float r = __fdividef(1.0f, s);
    float4* o = reinterpret_cast<float4*>(out + t * KC);
    o[0] = make_float4(e[0] * r,  e[1] * r,  e[2] * r,  e[3] * r);
    o[1] = make_float4(e[4] * r,  e[5] * r,  e[6] * r,  e[7] * r);
    o[2] = make_float4(e[8] * r,  e[9] * r,  e[10] * r, e[11] * r);
    o[3] = make_float4(e[12] * r, e[13] * r, e[14] * r, e[15] * r);
}

extern "C" void kernel_launch(void* const* d_in, const int* in_sizes, int n_in,
                              void* d_out, int out_size) {
    const float* x     = (const float*)d_in[0];
    const float* pi    = (const float*)d_in[1];
    const float* mu    = (const float*)d_in[2];
    const float* Sigma = (const float*)d_in[3];
    float* out = (float*)d_out;

    int n = in_sizes[0] / DD;

    // 16 warp-blocks (one per cluster) run concurrently on 16 SMs.
    gmm_precompute<<<KC, 32>>>(pi, mu, Sigma);

    void* gall_addr = nullptr;
    cudaGetSymbolAddress(&gall_addr, g_all);
    cudaMemcpyToSymbolAsync(c_all, gall_addr, sizeof(float) * NALL * KC, 0,
                            cudaMemcpyDeviceToDevice, 0);

    int block = 256;
    int grid  = (n + block - 1) / block;
    gmm_main<<<grid, block>>>(x, out, n);
}

// round 15
// speedup vs baseline: 1.1518x; 1.0024x over previous
#include <cuda_runtime.h>
#include <cuda_bf16.h>

#define KC 16
#define DD 16
#define NQUAD 136          // i<=j pairs
#define NFEAT 152          // 136 quad + 16 linear
#define NALL  (NFEAT + 1)  // + constants row

// Staging area written by the precompute kernel (single symbol -> single copy).
__device__ float g_all[NALL * KC];
// Constant-bank mirror: hot loop reads via uniform-path loads (LDCU).
__constant__ __align__(16) float c_all[NALL * KC];

// ---------------------------------------------------------------------------
// f32x2 packed helpers
// ---------------------------------------------------------------------------
__device__ __forceinline__ unsigned long long f2dup(float v) {
    unsigned long long r;
    asm("mov.b64 %0, {%1, %1};" : "=l"(r) : "f"(v));
    return r;
}
__device__ __forceinline__ unsigned long long f2fma(unsigned long long a, unsigned long long b,
                                                    unsigned long long c) {
    unsigned long long r;
    asm("fma.rn.f32x2 %0, %1, %2, %3;" : "=l"(r) : "l"(a), "l"(b), "l"(c));
    return r;
}
__device__ __forceinline__ void f2unpack(unsigned long long v, float& lo, float& hi) {
    asm("mov.b64 {%0, %1}, %2;" : "=f"(lo), "=f"(hi) : "l"(v));
}

// ---------------------------------------------------------------------------
// Precompute: one warp-block per cluster (16 blocks run on 16 SMs in
// parallel). Gauss-Jordan inverse of Sigma, logdet from pivots, b = P*mu.
// ---------------------------------------------------------------------------
__global__ void gmm_precompute(const float* __restrict__ pi,
                               const float* __restrict__ mu,
                               const float* __restrict__ Sigma) {
    const int w    = blockIdx.x;
    const int lane = threadIdx.x & 31;
    const int j    = lane & 15;

    float a[16], inv[16];
#pragma unroll
    for (int i = 0; i < 16; ++i) {
        a[i]   = Sigma[w * 256 + i * 16 + j];
        inv[i] = (i == j) ? 1.0f : 0.0f;
    }

    float logdet = 0.0f;
#pragma unroll
    for (int k = 0; k < 16; ++k) {
        float piv = __shfl_sync(0xffffffffu, a[k], k);
        logdet += logf(piv);
        float ip = 1.0f / piv;
        a[k]   *= ip;
        inv[k] *= ip;
#pragma unroll
        for (int i = 0; i < 16; ++i) {
            if (i != k) {
                float m = __shfl_sync(0xffffffffu, a[i], k);
                a[i]   = fmaf(-m, a[k],   a[i]);
                inv[i] = fmaf(-m, inv[k], inv[i]);
            }
        }
    }

    const float mu_j = mu[w * 16 + j];
    float bv[16];
#pragma unroll
    for (int i = 0; i < 16; ++i) {
        float v = inv[i] * mu_j;
        v += __shfl_xor_sync(0xffffffffu, v, 8);
        v += __shfl_xor_sync(0xffffffffu, v, 4);
        v += __shfl_xor_sync(0xffffffffu, v, 2);
        v += __shfl_xor_sync(0xffffffffu, v, 1);
        bv[i] = v;
    }
    float muPmu = 0.0f;
#pragma unroll
    for (int i = 0; i < 16; ++i) muPmu += bv[i] * mu[w * 16 + i];

    if (lane < 16) {
#pragma unroll
        for (int i = 0; i < 16; ++i) {
            if (i <= j) {
                float c = (i == j ? -0.5f : -1.0f) * inv[i];
                g_all[(j * (j + 1) / 2 + i) * KC + w] = c;
            }
        }
    }
    if (lane == 0) {
#pragma unroll
        for (int i = 0; i < 16; ++i) g_all[(NQUAD + i) * KC + w] = bv[i];
        g_all[NFEAT * KC + w] =
            logf(pi[w]) - 0.5f * logdet - 8.0f * 1.8378770664093453f - 0.5f * muPmu;
    }
}

// ---------------------------------------------------------------------------
// Main kernel: ONE point per thread, X scalar (16 regs), acc packs 2 clusters
// per f32x2 (16 regs). Per feature: 1 FMUL + 1 ALU dup-mov + 4 LDCU.128 +
// 8 f2fma. 39 regs measured -> raise residency to 6 CTAs/SM (75% occ); the
// previous (256,5) bound left register headroom (needs <=42) unused.
// ---------------------------------------------------------------------------
__global__ void __launch_bounds__(256, 6) gmm_main(const float* __restrict__ x,
                                                   float* __restrict__ out, int n) {
    long long t = (long long)blockIdx.x * blockDim.x + threadIdx.x;
    if (t >= n) return;

    const float4* x4 = reinterpret_cast<const float4*>(x + t * DD);
    float X[16];
#pragma unroll
    for (int q = 0; q < 4; ++q) {
        float4 v = x4[q];
        X[4 * q + 0] = v.x; X[4 * q + 1] = v.y; X[4 * q + 2] = v.z; X[4 * q + 3] = v.w;
    }

    const ulonglong2* cvec = reinterpret_cast<const ulonglong2*>(c_all);

    unsigned long long acc[8];
#pragma unroll
    for (int m = 0; m < 4; ++m) {
        ulonglong2 c = cvec[NFEAT * 4 + m];   // constants row
        acc[2 * m] = c.x; acc[2 * m + 1] = c.y;
    }

    // quadratic features (i<=j), feature p = j*(j+1)/2 + i
    int p = 0;
#pragma unroll
    for (int j = 0; j < 16; ++j) {
#pragma unroll
        for (int i = 0; i <= j; ++i) {
            unsigned long long f = f2dup(X[i] * X[j]);
#pragma unroll
            for (int m = 0; m < 4; ++m) {
                ulonglong2 cc = cvec[p * 4 + m];      // clusters 4m..4m+3
                acc[2 * m]     = f2fma(cc.x, f, acc[2 * m]);
                acc[2 * m + 1] = f2fma(cc.y, f, acc[2 * m + 1]);
            }
            ++p;
        }
    }
    // linear features
#pragma unroll
    for (int i = 0; i < 16; ++i) {
        unsigned long long f = f2dup(X[i]);
#pragma unroll
        for (int m = 0; m < 4; ++m) {
            ulonglong2 cc = cvec[(NQUAD + i) * 4 + m];
            acc[2 * m]     = f2fma(cc.x, f, acc[2 * m]);
            acc[2 * m + 1] = f2fma(cc.y, f, acc[2 * m + 1]);
        }
    }

    // unpack logits
    float l[16];
#pragma unroll
    for (int m = 0; m < 8; ++m) f2unpack(acc[m], l[2 * m], l[2 * m + 1]);

    // softmax + store
    float mx = l[0];
#pragma unroll
    for (int k = 1; k < 16; ++k) mx = fmaxf(mx, l[k]);
    float e[16], s = 0.0f;
#pragma unroll
    for (int k = 0; k < 16; ++k) { e[k] = __expf(l[k] - mx); s += e[k]; }
    float r = __fdividef(1.0f, s);
    float4* o = reinterpret_cast<float4*>(out + t * KC);
    o[0] = make_float4(e[0] * r,  e[1] * r,  e[2] * r,  e[3] * r);
    o[1] = make_float4(e[4] * r,  e[5] * r,  e[6] * r,  e[7] * r);
    o[2] = make_float4(e[8] * r,  e[9] * r,  e[10] * r, e[11] * r);
    o[3] = make_float4(e[12] * r, e[13] * r, e[14] * r, e[15] * r);
}

extern "C" void kernel_launch(void* const* d_in, const int* in_sizes, int n_in,
                              void* d_out, int out_size) {
    const float* x     = (const float*)d_in[0];
    const float* pi    = (const float*)d_in[1];
    const float* mu    = (const float*)d_in[2];
    const float* Sigma = (const float*)d_in[3];
    float* out = (float*)d_out;

    int n = in_sizes[0] / DD;

    // 16 warp-blocks (one per cluster) run concurrently on 16 SMs.
    gmm_precompute<<<KC, 32>>>(pi, mu, Sigma);

    void* gall_addr = nullptr;
    cudaGetSymbolAddress(&gall_addr, g_all);
    cudaMemcpyToSymbolAsync(c_all, gall_addr, sizeof(float) * NALL * KC, 0,
                            cudaMemcpyDeviceToDevice, 0);

    int block = 256;
    int grid  = (n + block - 1) / block;
    gmm_main<<<grid, block>>>(x, out, n);
}